// round 2
// baseline (speedup 1.0000x reference)
#include <cuda_runtime.h>
#include <math.h>

#define BATCH   64
#define SEQ     200
#define EMBED   64
#define NCAPS   50
#define R_TOT   3072
#define LOUT    96
#define ODIM    16

// ---------------- scratch (static device allocations; no cudaMalloc) -------
__device__ float g_cwt[576 * 256];                       // transposed conv weights [ek][ch]
__device__ float g_u[(size_t)BATCH * R_TOT * 8];         // primary capsules [b][r][i]
__device__ float g_blog[(size_t)NCAPS * R_TOT * BATCH];  // routing logits [c][r][b]
__device__ float g_m[R_TOT * BATCH];                     // softmax max  [r][b]
__device__ float g_invZ[R_TOT * BATCH];                  // softmax 1/Z  [r][b]
__device__ float g_s[BATCH * NCAPS * 16];                // s vectors [b][c][o]
__device__ float g_v[BATCH * NCAPS * 16];                // v vectors [b][c][o]
__device__ float g_h1[BATCH * 512];
__device__ float g_h2[BATCH * 1024];
__device__ int   g_amax[BATCH];

// ---------------- transpose conv weights: [ch][e][k] -> [e*9+k][ch] --------
__global__ void k_transpose_w(const float* __restrict__ conv_w) {
    int ek = blockIdx.x;          // 0..575
    int ch = threadIdx.x;         // 0..255
    g_cwt[ek * 256 + ch] = conv_w[ch * 576 + ek];
}

// ---------------- embedding + conv1d(k=9,s=2) + relu -> u ------------------
// grid (64 b, 6 l-tiles of 16), 256 threads (one channel each)
__global__ void k_conv(const int* __restrict__ x, const float* __restrict__ emb,
                       const float* __restrict__ conv_b) {
    int b = blockIdx.x;
    int l0 = blockIdx.y * 16;
    __shared__ float xs[39 * 64];   // s_rel in [0,38], 64 embed dims
    const int tid = threadIdx.x;
    for (int idx = tid; idx < 39 * 16; idx += 256) {
        int row = idx >> 4, col = idx & 15;
        int tok = x[b * SEQ + 2 * l0 + row];
        ((float4*)xs)[row * 16 + col] = ((const float4*)(emb + (size_t)tok * EMBED))[col];
    }
    __syncthreads();
    int ch = tid;
    float acc[16];
    float bias = conv_b[ch];
#pragma unroll
    for (int j = 0; j < 16; j++) acc[j] = bias;
    for (int e = 0; e < 64; e++) {
#pragma unroll
        for (int k = 0; k < 9; k++) {
            float w = g_cwt[(e * 9 + k) * 256 + ch];
#pragma unroll
            for (int j = 0; j < 16; j++)
                acc[j] = fmaf(xs[(2 * j + k) * 64 + e], w, acc[j]);
        }
    }
    int g = ch >> 3, i = ch & 7;
#pragma unroll
    for (int j = 0; j < 16; j++) {
        float val = acc[j] > 0.f ? acc[j] : 0.f;
        g_u[((size_t)b * R_TOT + g * LOUT + l0 + j) * 8 + i] = val;
    }
}

// ---------------- zero s ----------------------------------------------------
__global__ void k_zero_s() {
    int idx = blockIdx.x * 256 + threadIdx.x;
    if (idx < BATCH * NCAPS * 16) g_s[idx] = 0.f;
}

// ---------------- pass_s: s[b,c,o] += sum_r coeff * (u[b,r,:] @ W[c,r,:,:]) -
// grid (48 r-blocks of 64, 50 c), 256 threads.
// thread = (bg 0..15 -> 4 batches, rg 0..15 -> 4 routes); coeff folded into u
// so the 8x16 matmul accumulates straight into registers across the r-tile.
template <int MODE>   // 0 = uniform 1/50, 1 = softmax(b_log)
__global__ void k_pass_s(const float* __restrict__ W) {
    int c = blockIdx.y;
    int r0 = blockIdx.x * 64;
    __shared__ float4 Ws[64 * 32];      // 64 routes x 128 floats
    __shared__ float s_sh[64 * 16];
    const float4* Wg = (const float4*)(W + ((size_t)c * R_TOT + r0) * 128);
    for (int i = threadIdx.x; i < 2048; i += 256) Ws[i] = Wg[i];
    for (int i = threadIdx.x; i < 1024; i += 256) s_sh[i] = 0.f;
    __syncthreads();

    int bg = threadIdx.x & 15;
    int rg = threadIdx.x >> 4;
    int b0 = bg * 4;
    float acc[4][16];
#pragma unroll
    for (int j = 0; j < 4; j++)
#pragma unroll
        for (int o = 0; o < 16; o++) acc[j][o] = 0.f;

    for (int rr = 0; rr < 4; rr++) {
        int rl = rg * 4 + rr;
        int r = r0 + rl;
        float cf[4];
        if (MODE == 0) {
            cf[0] = cf[1] = cf[2] = cf[3] = 0.02f;
        } else {
            float4 bl = *(const float4*)(g_blog + ((size_t)c * R_TOT + r) * 64 + b0);
            float4 mm = *(const float4*)(g_m + r * 64 + b0);
            float4 iz = *(const float4*)(g_invZ + r * 64 + b0);
            cf[0] = __expf(bl.x - mm.x) * iz.x;
            cf[1] = __expf(bl.y - mm.y) * iz.y;
            cf[2] = __expf(bl.z - mm.z) * iz.z;
            cf[3] = __expf(bl.w - mm.w) * iz.w;
        }
        float su[4][8];
#pragma unroll
        for (int j = 0; j < 4; j++) {
            const float4* up = (const float4*)(g_u + ((size_t)(b0 + j) * R_TOT + r) * 8);
            float4 a = up[0], bb = up[1];
            su[j][0] = cf[j] * a.x;  su[j][1] = cf[j] * a.y;
            su[j][2] = cf[j] * a.z;  su[j][3] = cf[j] * a.w;
            su[j][4] = cf[j] * bb.x; su[j][5] = cf[j] * bb.y;
            su[j][6] = cf[j] * bb.z; su[j][7] = cf[j] * bb.w;
        }
        const float4* wrow = &Ws[rl * 32];
#pragma unroll
        for (int i = 0; i < 8; i++) {
#pragma unroll
            for (int o4 = 0; o4 < 4; o4++) {
                float4 w = wrow[i * 4 + o4];
#pragma unroll
                for (int j = 0; j < 4; j++) {
                    acc[j][o4 * 4 + 0] = fmaf(su[j][i], w.x, acc[j][o4 * 4 + 0]);
                    acc[j][o4 * 4 + 1] = fmaf(su[j][i], w.y, acc[j][o4 * 4 + 1]);
                    acc[j][o4 * 4 + 2] = fmaf(su[j][i], w.z, acc[j][o4 * 4 + 2]);
                    acc[j][o4 * 4 + 3] = fmaf(su[j][i], w.w, acc[j][o4 * 4 + 3]);
                }
            }
        }
    }
#pragma unroll
    for (int j = 0; j < 4; j++)
#pragma unroll
        for (int o = 0; o < 16; o++)
            atomicAdd(&s_sh[(b0 + j) * 16 + o], acc[j][o]);
    __syncthreads();
    for (int i = threadIdx.x; i < 1024; i += 256) {
        int b = i >> 4, o = i & 15;
        atomicAdd(&g_s[((size_t)b * NCAPS + c) * 16 + o], s_sh[i]);
    }
}

// ---------------- pass_agree: b_log[c,r,b] (+)= u_hat . v -------------------
template <int ACC>    // 0 = write, 1 = accumulate
__global__ void k_pass_agree(const float* __restrict__ W) {
    int c = blockIdx.y;
    int r0 = blockIdx.x * 64;
    __shared__ float4 Ws[64 * 32];
    const float4* Wg = (const float4*)(W + ((size_t)c * R_TOT + r0) * 128);
    for (int i = threadIdx.x; i < 2048; i += 256) Ws[i] = Wg[i];
    __syncthreads();

    int bg = threadIdx.x & 15;
    int rg = threadIdx.x >> 4;
    int b0 = bg * 4;
    float vv[4][16];
#pragma unroll
    for (int j = 0; j < 4; j++) {
        const float4* vp = (const float4*)(g_v + ((size_t)(b0 + j) * NCAPS + c) * 16);
#pragma unroll
        for (int o4 = 0; o4 < 4; o4++) {
            float4 t = vp[o4];
            vv[j][o4 * 4 + 0] = t.x; vv[j][o4 * 4 + 1] = t.y;
            vv[j][o4 * 4 + 2] = t.z; vv[j][o4 * 4 + 3] = t.w;
        }
    }
    for (int rr = 0; rr < 4; rr++) {
        int rl = rg * 4 + rr;
        int r = r0 + rl;
        float g[4][8];
#pragma unroll
        for (int j = 0; j < 4; j++)
#pragma unroll
            for (int i = 0; i < 8; i++) g[j][i] = 0.f;
        const float4* wrow = &Ws[rl * 32];
#pragma unroll
        for (int i = 0; i < 8; i++) {
#pragma unroll
            for (int o4 = 0; o4 < 4; o4++) {
                float4 w = wrow[i * 4 + o4];
#pragma unroll
                for (int j = 0; j < 4; j++) {
                    g[j][i] = fmaf(w.x, vv[j][o4 * 4 + 0], g[j][i]);
                    g[j][i] = fmaf(w.y, vv[j][o4 * 4 + 1], g[j][i]);
                    g[j][i] = fmaf(w.z, vv[j][o4 * 4 + 2], g[j][i]);
                    g[j][i] = fmaf(w.w, vv[j][o4 * 4 + 3], g[j][i]);
                }
            }
        }
        float add[4];
#pragma unroll
        for (int j = 0; j < 4; j++) {
            const float4* up = (const float4*)(g_u + ((size_t)(b0 + j) * R_TOT + r) * 8);
            float4 a = up[0], bb = up[1];
            add[j] = a.x * g[j][0] + a.y * g[j][1] + a.z * g[j][2] + a.w * g[j][3]
                   + bb.x * g[j][4] + bb.y * g[j][5] + bb.z * g[j][6] + bb.w * g[j][7];
        }
        float* dst = g_blog + ((size_t)c * R_TOT + r) * 64 + b0;
        float4 res = make_float4(add[0], add[1], add[2], add[3]);
        if (ACC) {
            float4 old = *(float4*)dst;
            res.x += old.x; res.y += old.y; res.z += old.z; res.w += old.w;
        }
        *(float4*)dst = res;
    }
}

// ---------------- per-(r,b) softmax stats over c ----------------------------
__global__ void k_softmax_prep() {
    int idx = blockIdx.x * 256 + threadIdx.x;   // = r*64+b, 196608 total
    float mx = -1e30f;
    for (int c = 0; c < NCAPS; c++) {
        float v = g_blog[(size_t)c * R_TOT * 64 + idx];
        mx = fmaxf(mx, v);
    }
    float sum = 0.f;
    for (int c = 0; c < NCAPS; c++) {
        float v = g_blog[(size_t)c * R_TOT * 64 + idx];
        sum += __expf(v - mx);
    }
    g_m[idx] = mx;
    g_invZ[idx] = 1.f / sum;
}

// ---------------- squash ----------------------------------------------------
__global__ void k_squash() {
    int idx = blockIdx.x * 256 + threadIdx.x;
    if (idx >= BATCH * NCAPS) return;
    const float4* sp = (const float4*)(g_s + (size_t)idx * 16);
    float4 s0 = sp[0], s1 = sp[1], s2 = sp[2], s3 = sp[3];
    float nsq = s0.x * s0.x + s0.y * s0.y + s0.z * s0.z + s0.w * s0.w
              + s1.x * s1.x + s1.y * s1.y + s1.z * s1.z + s1.w * s1.w
              + s2.x * s2.x + s2.y * s2.y + s2.z * s2.z + s2.w * s2.w
              + s3.x * s3.x + s3.y * s3.y + s3.z * s3.z + s3.w * s3.w;
    float norm = sqrtf(nsq);
    float f = nsq / (1.f + nsq) / (norm + 1e-8f);
    float4* vp = (float4*)(g_v + (size_t)idx * 16);
    vp[0] = make_float4(f * s0.x, f * s0.y, f * s0.z, f * s0.w);
    vp[1] = make_float4(f * s1.x, f * s1.y, f * s1.z, f * s1.w);
    vp[2] = make_float4(f * s2.x, f * s2.y, f * s2.z, f * s2.w);
    vp[3] = make_float4(f * s3.x, f * s3.y, f * s3.z, f * s3.w);
}

// ---------------- lengths + argmax ------------------------------------------
__global__ void k_lengths(float* __restrict__ out_len) {
    int b = threadIdx.x;
    if (b >= BATCH) return;
    float best = -1.f; int bi = 0;
    for (int c = 0; c < NCAPS; c++) {
        const float4* vp = (const float4*)(g_v + ((size_t)b * NCAPS + c) * 16);
        float nsq = 0.f;
#pragma unroll
        for (int o4 = 0; o4 < 4; o4++) {
            float4 t = vp[o4];
            nsq += t.x * t.x + t.y * t.y + t.z * t.z + t.w * t.w;
        }
        float len = sqrtf(nsq);
        out_len[b * NCAPS + c] = len;
        if (len > best) { best = len; bi = c; }
    }
    g_amax[b] = bi;
}

// ---------------- MLP layer 1 (16-sparse input) -----------------------------
__global__ void k_mlp1(const float* __restrict__ w1, const float* __restrict__ b1) {
    int b = blockIdx.x;
    int cb = g_amax[b];
    __shared__ float vv[16];
    if (threadIdx.x < 16)
        vv[threadIdx.x] = g_v[((size_t)b * NCAPS + cb) * 16 + threadIdx.x];
    __syncthreads();
    int n = threadIdx.x;
    float acc = b1[n];
#pragma unroll
    for (int o = 0; o < 16; o++)
        acc = fmaf(vv[o], w1[(size_t)(cb * 16 + o) * 512 + n], acc);
    g_h1[b * 512 + n] = acc > 0.f ? acc : 0.f;
}

// ---------------- MLP layer 2 ----------------------------------------------
__global__ void k_mlp2(const float* __restrict__ w2, const float* __restrict__ b2) {
    int b = blockIdx.x;
    __shared__ float hh[512];
    for (int i = threadIdx.x; i < 512; i += 256) hh[i] = g_h1[b * 512 + i];
    __syncthreads();
    int n0 = threadIdx.x * 4;
    float4 acc = *(const float4*)(b2 + n0);
    for (int k = 0; k < 512; k++) {
        float h = hh[k];
        float4 w = *(const float4*)(w2 + (size_t)k * 1024 + n0);
        acc.x = fmaf(h, w.x, acc.x);
        acc.y = fmaf(h, w.y, acc.y);
        acc.z = fmaf(h, w.z, acc.z);
        acc.w = fmaf(h, w.w, acc.w);
    }
    acc.x = acc.x > 0.f ? acc.x : 0.f;
    acc.y = acc.y > 0.f ? acc.y : 0.f;
    acc.z = acc.z > 0.f ? acc.z : 0.f;
    acc.w = acc.w > 0.f ? acc.w : 0.f;
    *(float4*)(g_h2 + (size_t)b * 1024 + n0) = acc;
}

// ---------------- MLP layer 3: (64x1024)@(1024x19000) + sigmoid -------------
// grid = 149 n-tiles of 128; each block computes all 64 batch rows so w3 is
// read exactly once from HBM. 256 threads, thread tile 8b x 4n.
__global__ void k_mlp3(const float* __restrict__ w3, const float* __restrict__ b3,
                       float* __restrict__ out_recon) {
    int ncol0 = blockIdx.x * 128;
    __shared__ float h2s[64 * 32];
    __shared__ float w3s[32 * 128];
    int tid = threadIdx.x;
    int bt = tid >> 5, ntid = tid & 31;
    int b0 = bt * 8;
    int n_off = ntid * 4;
    float4 acc[8];
#pragma unroll
    for (int j = 0; j < 8; j++) acc[j] = make_float4(0.f, 0.f, 0.f, 0.f);

    for (int kc = 0; kc < 32; kc++) {
        for (int idx = tid; idx < 64 * 32; idx += 256) {
            int bb = idx >> 5, kk = idx & 31;
            h2s[bb * 32 + kk] = g_h2[(size_t)bb * 1024 + kc * 32 + kk];
        }
        for (int idx = tid; idx < 32 * 32; idx += 256) {
            int kk = idx >> 5, jj = idx & 31;
            int col = ncol0 + jj * 4;
            float4 val;
            const float* row = w3 + (size_t)(kc * 32 + kk) * 19000;
            if (col + 3 < 19000) {
                val = *(const float4*)(row + col);
            } else {
                val.x = (col + 0 < 19000) ? row[col + 0] : 0.f;
                val.y = (col + 1 < 19000) ? row[col + 1] : 0.f;
                val.z = (col + 2 < 19000) ? row[col + 2] : 0.f;
                val.w = (col + 3 < 19000) ? row[col + 3] : 0.f;
            }
            *(float4*)&w3s[kk * 128 + jj * 4] = val;
        }
        __syncthreads();
        for (int kk = 0; kk < 32; kk++) {
            float4 w = *(const float4*)&w3s[kk * 128 + n_off];
#pragma unroll
            for (int j = 0; j < 8; j++) {
                float h = h2s[(b0 + j) * 32 + kk];
                acc[j].x = fmaf(h, w.x, acc[j].x);
                acc[j].y = fmaf(h, w.y, acc[j].y);
                acc[j].z = fmaf(h, w.z, acc[j].z);
                acc[j].w = fmaf(h, w.w, acc[j].w);
            }
        }
        __syncthreads();
    }
    int n = ncol0 + n_off;
#pragma unroll
    for (int j = 0; j < 8; j++) {
        int b = b0 + j;
        float* ap = (float*)&acc[j];
#pragma unroll
        for (int e = 0; e < 4; e++) {
            int nn = n + e;
            if (nn < 19000) {
                float val = ap[e] + b3[nn];
                out_recon[(size_t)b * 19000 + nn] = 1.f / (1.f + __expf(-val));
            }
        }
    }
}

// ---------------- launch ----------------------------------------------------
extern "C" void kernel_launch(void* const* d_in, const int* in_sizes, int n_in,
                              void* d_out, int out_size) {
    const int*   x      = (const int*)d_in[0];
    const float* emb    = (const float*)d_in[1];
    const float* conv_w = (const float*)d_in[2];
    const float* conv_b = (const float*)d_in[3];
    const float* W      = (const float*)d_in[4];
    const float* w1     = (const float*)d_in[5];
    const float* b1     = (const float*)d_in[6];
    const float* w2     = (const float*)d_in[7];
    const float* b2     = (const float*)d_in[8];
    const float* w3     = (const float*)d_in[9];
    const float* b3     = (const float*)d_in[10];
    float* out       = (float*)d_out;
    float* out_len   = out;                       // [64,50]
    float* out_recon = out + BATCH * NCAPS;       // [64,19000]

    dim3 pass_grid(48, 50);

    k_transpose_w<<<576, 256>>>(conv_w);
    k_conv<<<dim3(64, 6), 256>>>(x, emb, conv_b);

    // routing iter 0: uniform coupling
    k_zero_s<<<200, 256>>>();
    k_pass_s<0><<<pass_grid, 256>>>(W);
    k_squash<<<13, 256>>>();

    // iter 1
    k_pass_agree<0><<<pass_grid, 256>>>(W);
    k_softmax_prep<<<768, 256>>>();
    k_zero_s<<<200, 256>>>();
    k_pass_s<1><<<pass_grid, 256>>>(W);
    k_squash<<<13, 256>>>();

    // iter 2
    k_pass_agree<1><<<pass_grid, 256>>>(W);
    k_softmax_prep<<<768, 256>>>();
    k_zero_s<<<200, 256>>>();
    k_pass_s<1><<<pass_grid, 256>>>(W);
    k_squash<<<13, 256>>>();

    // heads
    k_lengths<<<1, 64>>>(out_len);
    k_mlp1<<<64, 512>>>(w1, b1);
    k_mlp2<<<64, 256>>>(w2, b2);
    k_mlp3<<<149, 256>>>(w3, b3, out_recon);
}

// round 4
// speedup vs baseline: 1.8308x; 1.8308x over previous
#include <cuda_runtime.h>
#include <math.h>

#define BATCH   64
#define SEQ     200
#define EMBED   64
#define NCAPS   50
#define R_TOT   3072
#define LOUT    96
#define ODIM    16
#define RT      32          // routes per block in pass kernels
#define NRB     96          // R_TOT / RT

// ---------------- scratch (static device allocations; no cudaMalloc) -------
__device__ __align__(16) float g_cwt[576 * 256];                        // [ek][ch]
__device__ __align__(16) float g_u[(size_t)BATCH * R_TOT * 8];          // [b][r][i]
__device__ __align__(16) float g_blog[(size_t)NCAPS * R_TOT * BATCH];   // [c][r][b]
__device__ __align__(16) float g_coeff[(size_t)NCAPS * R_TOT * BATCH];  // [c][r][b]
__device__ __align__(16) float g_spart[(size_t)NCAPS * NRB * BATCH * 16]; // [c][rb][b][o]
__device__ __align__(16) float g_v[BATCH * NCAPS * 16];                 // [b][c][o]
__device__ __align__(16) float g_h1[BATCH * 512];
__device__ __align__(16) float g_h2[BATCH * 1024];
__device__ int   g_amax[BATCH];

// ---------------- f32x2 helpers --------------------------------------------
__device__ __forceinline__ unsigned long long pk2(float a, float b) {
    unsigned long long r;
    asm("mov.b64 %0, {%1, %2};" : "=l"(r) : "f"(a), "f"(b));
    return r;
}
__device__ __forceinline__ void fma2(unsigned long long& d, unsigned long long a,
                                     unsigned long long b) {
    asm("fma.rn.f32x2 %0, %1, %2, %0;" : "+l"(d) : "l"(a), "l"(b));
}
__device__ __forceinline__ unsigned long long add2(unsigned long long a,
                                                   unsigned long long b) {
    unsigned long long r;
    asm("add.rn.f32x2 %0, %1, %2;" : "=l"(r) : "l"(a), "l"(b));
    return r;
}
__device__ __forceinline__ float2 upk(unsigned long long v) {
    float2 f;
    asm("mov.b64 {%0, %1}, %2;" : "=f"(f.x), "=f"(f.y) : "l"(v));
    return f;
}

// ---------------- transpose conv weights: [ch][e][k] -> [e*9+k][ch] --------
__global__ void k_transpose_w(const float* __restrict__ conv_w) {
    int ek = blockIdx.x;
    int ch = threadIdx.x;
    g_cwt[ek * 256 + ch] = conv_w[ch * 576 + ek];
}

// ---------------- embedding + conv1d(k=9,s=2) + relu -> u ------------------
__global__ void k_conv(const int* __restrict__ x, const float* __restrict__ emb,
                       const float* __restrict__ conv_b) {
    int b = blockIdx.x;
    int l0 = blockIdx.y * 16;
    __shared__ float xs[39 * 64];
    const int tid = threadIdx.x;
    for (int idx = tid; idx < 39 * 16; idx += 256) {
        int row = idx >> 4, col = idx & 15;
        int tok = x[b * SEQ + 2 * l0 + row];
        ((float4*)xs)[row * 16 + col] = ((const float4*)(emb + (size_t)tok * EMBED))[col];
    }
    __syncthreads();
    int ch = tid;
    float acc[16];
    float bias = conv_b[ch];
#pragma unroll
    for (int j = 0; j < 16; j++) acc[j] = bias;
    for (int e = 0; e < 64; e++) {
#pragma unroll
        for (int k = 0; k < 9; k++) {
            float w = g_cwt[(e * 9 + k) * 256 + ch];
#pragma unroll
            for (int j = 0; j < 16; j++)
                acc[j] = fmaf(xs[(2 * j + k) * 64 + e], w, acc[j]);
        }
    }
    int g = ch >> 3, i = ch & 7;
#pragma unroll
    for (int j = 0; j < 16; j++) {
        float val = acc[j] > 0.f ? acc[j] : 0.f;
        g_u[((size_t)b * R_TOT + g * LOUT + l0 + j) * 8 + i] = val;
    }
}

// ---------------- pass_s: partial s over an r-block -------------------------
// grid (96 rb, 50 c), 256 thr. thread: rg = tid&7 (4 routes rl = rr*8+rg),
// bg = tid>>3 (2 batches). acc packed f32x2 over o-pairs. Butterfly-reduce
// over the 8 rg lanes, rg==0 writes g_spart[c][rb][b][o]. No atomics.
#define CF_STRIDE 68
#define SMEM_S (RT * 132 + RT * 516 + RT * CF_STRIDE)
template <int MODE>   // 0 = uniform 1/50, 1 = g_coeff
__global__ void __launch_bounds__(256, 2) k_pass_s(const float* __restrict__ W) {
    extern __shared__ float sh[];
    float* Ws    = sh;                       // RT rows x 132 (128 used)
    float* u_sh  = sh + RT * 132;            // RT rows x 516 (512 used)
    float* cf_sh = sh + RT * 132 + RT * 516; // RT rows x 68  (64 used)

    int c = blockIdx.y;
    int rb = blockIdx.x;
    int r0 = rb * RT;
    int tid = threadIdx.x;

    // stage W (coalesced)
    const float4* Wg = (const float4*)(W + ((size_t)c * R_TOT + r0) * 128);
    for (int idx = tid; idx < RT * 32; idx += 256) {
        int rl = idx >> 5, q = idx & 31;
        *(float4*)&Ws[rl * 132 + q * 4] = Wg[idx];
    }
    // stage u (coalesced: 1KB contiguous per batch)
    for (int idx = tid; idx < BATCH * RT * 2; idx += 256) {
        int b = idx >> 6;
        int t = idx & 63;
        int rl = t >> 1, i4 = (t & 1) * 4;
        float4 v = *(const float4*)(g_u + ((size_t)b * R_TOT + r0 + rl) * 8 + i4);
        *(float4*)&u_sh[rl * 516 + b * 8 + i4] = v;
    }
    if (MODE == 1) {
        for (int idx = tid; idx < RT * 16; idx += 256) {
            int rl = idx >> 4, b4 = (idx & 15) * 4;
            float4 v = *(const float4*)(g_coeff + ((size_t)c * R_TOT + r0 + rl) * 64 + b4);
            *(float4*)&cf_sh[rl * CF_STRIDE + b4] = v;
        }
    }
    __syncthreads();

    int rg = tid & 7;
    int bg = tid >> 3;
    int b0 = bg * 2;

    unsigned long long acc0[8], acc1[8];
#pragma unroll
    for (int k = 0; k < 8; k++) { acc0[k] = 0ull; acc1[k] = 0ull; }

#pragma unroll
    for (int rr = 0; rr < 4; rr++) {
        int rl = rr * 8 + rg;
        float cf0, cf1;
        if (MODE == 0) { cf0 = cf1 = 0.02f; }
        else {
            float2 t = *(const float2*)&cf_sh[rl * CF_STRIDE + b0];
            cf0 = t.x; cf1 = t.y;
        }
        const float* up = &u_sh[rl * 516 + b0 * 8];
        float4 a0 = *(const float4*)(up);
        float4 a1 = *(const float4*)(up + 4);
        float4 c0 = *(const float4*)(up + 8);
        float4 c1 = *(const float4*)(up + 12);
        float su0[8] = {cf0 * a0.x, cf0 * a0.y, cf0 * a0.z, cf0 * a0.w,
                        cf0 * a1.x, cf0 * a1.y, cf0 * a1.z, cf0 * a1.w};
        float su1[8] = {cf1 * c0.x, cf1 * c0.y, cf1 * c0.z, cf1 * c0.w,
                        cf1 * c1.x, cf1 * c1.y, cf1 * c1.z, cf1 * c1.w};
        const float* wrow = &Ws[rl * 132];
#pragma unroll
        for (int i = 0; i < 8; i++) {
            unsigned long long s0 = pk2(su0[i], su0[i]);
            unsigned long long s1 = pk2(su1[i], su1[i]);
#pragma unroll
            for (int o4 = 0; o4 < 4; o4++) {
                ulonglong2 wp = *(const ulonglong2*)&wrow[i * 16 + o4 * 4];
                fma2(acc0[o4 * 2 + 0], s0, wp.x);
                fma2(acc0[o4 * 2 + 1], s0, wp.y);
                fma2(acc1[o4 * 2 + 0], s1, wp.x);
                fma2(acc1[o4 * 2 + 1], s1, wp.y);
            }
        }
    }
    // reduce over the 8 rg lanes (contiguous in warp)
#pragma unroll
    for (int m = 1; m <= 4; m <<= 1) {
#pragma unroll
        for (int k = 0; k < 8; k++) {
            acc0[k] = add2(acc0[k], __shfl_xor_sync(0xffffffffu, acc0[k], m));
            acc1[k] = add2(acc1[k], __shfl_xor_sync(0xffffffffu, acc1[k], m));
        }
    }
    if (rg == 0) {
        unsigned long long* dst =
            (unsigned long long*)(g_spart + (((size_t)c * NRB + rb) * BATCH + b0) * 16);
#pragma unroll
        for (int k = 0; k < 8; k++) dst[k] = acc0[k];
#pragma unroll
        for (int k = 0; k < 8; k++) dst[8 + k] = acc1[k];
    }
}

// ---------------- reduce partials over rb + squash -> v ---------------------
__global__ void k_finalize_v() {
    int gid = blockIdx.x * 256 + threadIdx.x;   // (b*50+c)*16 + o, 51200 total
    int o = gid & 15;
    int bc = gid >> 4;
    int b = bc / NCAPS;
    int c = bc % NCAPS;
    float s = 0.f;
#pragma unroll 8
    for (int rb = 0; rb < NRB; rb++)
        s += g_spart[(((size_t)c * NRB + rb) * BATCH + b) * 16 + o];
    float nsq = s * s;
#pragma unroll
    for (int m = 1; m <= 8; m <<= 1)
        nsq += __shfl_xor_sync(0xffffffffu, nsq, m);
    float norm = sqrtf(nsq);
    float f = nsq / (1.f + nsq) / (norm + 1e-8f);
    g_v[gid] = f * s;
}

// ---------------- pass_agree: b_log[c,r,b] (+)= u_hat . v -------------------
#define SMEM_A (RT * 132 + RT * 516 + BATCH * 16)
template <int ACC>
__global__ void __launch_bounds__(256, 2) k_pass_agree(const float* __restrict__ W) {
    extern __shared__ float sh[];
    float* Ws   = sh;
    float* u_sh = sh + RT * 132;
    float* v_sh = sh + RT * 132 + RT * 516;

    int c = blockIdx.y;
    int rb = blockIdx.x;
    int r0 = rb * RT;
    int tid = threadIdx.x;

    const float4* Wg = (const float4*)(W + ((size_t)c * R_TOT + r0) * 128);
    for (int idx = tid; idx < RT * 32; idx += 256) {
        int rl = idx >> 5, q = idx & 31;
        *(float4*)&Ws[rl * 132 + q * 4] = Wg[idx];
    }
    for (int idx = tid; idx < BATCH * RT * 2; idx += 256) {
        int b = idx >> 6;
        int t = idx & 63;
        int rl = t >> 1, i4 = (t & 1) * 4;
        float4 v = *(const float4*)(g_u + ((size_t)b * R_TOT + r0 + rl) * 8 + i4);
        *(float4*)&u_sh[rl * 516 + b * 8 + i4] = v;
    }
    // v tile: all 64 batches for this c
    {
        int b = tid >> 2, o4 = (tid & 3) * 4;
        *(float4*)&v_sh[b * 16 + o4] =
            *(const float4*)(g_v + ((size_t)b * NCAPS + c) * 16 + o4);
    }
    __syncthreads();

    int rg = tid & 7;
    int bg = tid >> 3;
    int b0 = bg * 2;

    unsigned long long vp0[8], vp1[8];
    const unsigned long long* vr = (const unsigned long long*)&v_sh[b0 * 16];
#pragma unroll
    for (int k = 0; k < 8; k++) { vp0[k] = vr[k]; vp1[k] = vr[8 + k]; }

#pragma unroll
    for (int rr = 0; rr < 4; rr++) {
        int rl = rr * 8 + rg;
        int r = r0 + rl;
        const float* wrow = &Ws[rl * 132];
        float gg0[8], gg1[8];
#pragma unroll
        for (int i = 0; i < 8; i++) {
            unsigned long long gi0 = 0ull, gi1 = 0ull;
#pragma unroll
            for (int o4 = 0; o4 < 4; o4++) {
                ulonglong2 wp = *(const ulonglong2*)&wrow[i * 16 + o4 * 4];
                fma2(gi0, wp.x, vp0[o4 * 2 + 0]);
                fma2(gi0, wp.y, vp0[o4 * 2 + 1]);
                fma2(gi1, wp.x, vp1[o4 * 2 + 0]);
                fma2(gi1, wp.y, vp1[o4 * 2 + 1]);
            }
            float2 t0 = upk(gi0), t1 = upk(gi1);
            gg0[i] = t0.x + t0.y;
            gg1[i] = t1.x + t1.y;
        }
        const float* up = &u_sh[rl * 516 + b0 * 8];
        float4 a0 = *(const float4*)(up);
        float4 a1 = *(const float4*)(up + 4);
        float4 c0 = *(const float4*)(up + 8);
        float4 c1 = *(const float4*)(up + 12);
        float add0 = a0.x * gg0[0] + a0.y * gg0[1] + a0.z * gg0[2] + a0.w * gg0[3]
                   + a1.x * gg0[4] + a1.y * gg0[5] + a1.z * gg0[6] + a1.w * gg0[7];
        float add1 = c0.x * gg1[0] + c0.y * gg1[1] + c0.z * gg1[2] + c0.w * gg1[3]
                   + c1.x * gg1[4] + c1.y * gg1[5] + c1.z * gg1[6] + c1.w * gg1[7];
        float* dst = g_blog + ((size_t)c * R_TOT + r) * 64 + b0;
        float2 res = make_float2(add0, add1);
        if (ACC) {
            float2 old = *(const float2*)dst;
            res.x += old.x; res.y += old.y;
        }
        *(float2*)dst = res;
    }
}

// ---------------- coeff = softmax_c(b_log) ----------------------------------
__global__ void k_coeff() {
    int idx = blockIdx.x * 256 + threadIdx.x;   // r*64+b, 196608 total
    float e[NCAPS];
    float mx = -1e30f;
#pragma unroll
    for (int c = 0; c < NCAPS; c++) {
        e[c] = g_blog[(size_t)c * (R_TOT * 64) + idx];
        mx = fmaxf(mx, e[c]);
    }
    float sum = 0.f;
#pragma unroll
    for (int c = 0; c < NCAPS; c++) {
        e[c] = __expf(e[c] - mx);
        sum += e[c];
    }
    float iz = 1.f / sum;
#pragma unroll
    for (int c = 0; c < NCAPS; c++)
        g_coeff[(size_t)c * (R_TOT * 64) + idx] = e[c] * iz;
}

// ---------------- lengths + argmax ------------------------------------------
__global__ void k_lengths(float* __restrict__ out_len) {
    int b = threadIdx.x;
    if (b >= BATCH) return;
    float best = -1.f; int bi = 0;
    for (int c = 0; c < NCAPS; c++) {
        const float4* vp = (const float4*)(g_v + ((size_t)b * NCAPS + c) * 16);
        float nsq = 0.f;
#pragma unroll
        for (int o4 = 0; o4 < 4; o4++) {
            float4 t = vp[o4];
            nsq += t.x * t.x + t.y * t.y + t.z * t.z + t.w * t.w;
        }
        float len = sqrtf(nsq);
        out_len[b * NCAPS + c] = len;
        if (len > best) { best = len; bi = c; }
    }
    g_amax[b] = bi;
}

// ---------------- MLP layer 1 (16-sparse input) -----------------------------
__global__ void k_mlp1(const float* __restrict__ w1, const float* __restrict__ b1) {
    int b = blockIdx.x;
    int cb = g_amax[b];
    __shared__ float vv[16];
    if (threadIdx.x < 16)
        vv[threadIdx.x] = g_v[((size_t)b * NCAPS + cb) * 16 + threadIdx.x];
    __syncthreads();
    int n = threadIdx.x;
    float acc = b1[n];
#pragma unroll
    for (int o = 0; o < 16; o++)
        acc = fmaf(vv[o], w1[(size_t)(cb * 16 + o) * 512 + n], acc);
    g_h1[b * 512 + n] = acc > 0.f ? acc : 0.f;
}

// ---------------- MLP layer 2 ----------------------------------------------
__global__ void k_mlp2(const float* __restrict__ w2, const float* __restrict__ b2) {
    int b = blockIdx.x;
    __shared__ float hh[512];
    for (int i = threadIdx.x; i < 512; i += 256) hh[i] = g_h1[b * 512 + i];
    __syncthreads();
    int n0 = threadIdx.x * 4;
    float4 acc = *(const float4*)(b2 + n0);
    for (int k = 0; k < 512; k++) {
        float h = hh[k];
        float4 w = *(const float4*)(w2 + (size_t)k * 1024 + n0);
        acc.x = fmaf(h, w.x, acc.x);
        acc.y = fmaf(h, w.y, acc.y);
        acc.z = fmaf(h, w.z, acc.z);
        acc.w = fmaf(h, w.w, acc.w);
    }
    acc.x = acc.x > 0.f ? acc.x : 0.f;
    acc.y = acc.y > 0.f ? acc.y : 0.f;
    acc.z = acc.z > 0.f ? acc.z : 0.f;
    acc.w = acc.w > 0.f ? acc.w : 0.f;
    *(float4*)(g_h2 + (size_t)b * 1024 + n0) = acc;
}

// ---------------- MLP layer 3 (f32x2 over batch pairs) ----------------------
// grid = 149 n-tiles of 128; each block computes all 64 batch rows.
// thread: bt = tid>>5 -> 8 batches (4 pairs), ntid = tid&31 -> 4 n columns.
__global__ void k_mlp3(const float* __restrict__ w3, const float* __restrict__ b3,
                       float* __restrict__ out_recon) {
    int ncol0 = blockIdx.x * 128;
    __shared__ unsigned long long h2p[32 * 33];   // [b-pair][kk], padded
    __shared__ float w3s[32 * 128];
    int tid = threadIdx.x;
    int bt = tid >> 5, ntid = tid & 31;
    int bp0 = bt * 4;                 // first batch-pair
    int n_off = ntid * 4;
    unsigned long long acc2[4][4];
#pragma unroll
    for (int jp = 0; jp < 4; jp++)
#pragma unroll
        for (int e = 0; e < 4; e++) acc2[jp][e] = 0ull;

    for (int kc = 0; kc < 32; kc++) {
        for (int idx = tid; idx < 32 * 32; idx += 256) {
            int bp = idx >> 5, kk = idx & 31;
            float lo = g_h2[(size_t)(2 * bp) * 1024 + kc * 32 + kk];
            float hi = g_h2[(size_t)(2 * bp + 1) * 1024 + kc * 32 + kk];
            h2p[bp * 33 + kk] = pk2(lo, hi);
        }
        for (int idx = tid; idx < 32 * 32; idx += 256) {
            int kk = idx >> 5, jj = idx & 31;
            int col = ncol0 + jj * 4;
            float4 val;
            const float* row = w3 + (size_t)(kc * 32 + kk) * 19000;
            if (col + 3 < 19000) {
                val = *(const float4*)(row + col);
            } else {
                val.x = (col + 0 < 19000) ? row[col + 0] : 0.f;
                val.y = (col + 1 < 19000) ? row[col + 1] : 0.f;
                val.z = (col + 2 < 19000) ? row[col + 2] : 0.f;
                val.w = (col + 3 < 19000) ? row[col + 3] : 0.f;
            }
            *(float4*)&w3s[kk * 128 + jj * 4] = val;
        }
        __syncthreads();
        for (int kk = 0; kk < 32; kk++) {
            float4 w = *(const float4*)&w3s[kk * 128 + n_off];
            unsigned long long wp0 = pk2(w.x, w.x);
            unsigned long long wp1 = pk2(w.y, w.y);
            unsigned long long wp2 = pk2(w.z, w.z);
            unsigned long long wp3 = pk2(w.w, w.w);
#pragma unroll
            for (int jp = 0; jp < 4; jp++) {
                unsigned long long h = h2p[(bp0 + jp) * 33 + kk];
                fma2(acc2[jp][0], h, wp0);
                fma2(acc2[jp][1], h, wp1);
                fma2(acc2[jp][2], h, wp2);
                fma2(acc2[jp][3], h, wp3);
            }
        }
        __syncthreads();
    }
    int n = ncol0 + n_off;
#pragma unroll
    for (int jp = 0; jp < 4; jp++) {
        int b_even = (bp0 + jp) * 2;
#pragma unroll
        for (int e = 0; e < 4; e++) {
            int nn = n + e;
            if (nn < 19000) {
                float2 t = upk(acc2[jp][e]);
                float bias = b3[nn];
                float v0 = t.x + bias, v1 = t.y + bias;
                out_recon[(size_t)b_even * 19000 + nn] = 1.f / (1.f + __expf(-v0));
                out_recon[(size_t)(b_even + 1) * 19000 + nn] = 1.f / (1.f + __expf(-v1));
            }
        }
    }
}

// ---------------- launch ----------------------------------------------------
extern "C" void kernel_launch(void* const* d_in, const int* in_sizes, int n_in,
                              void* d_out, int out_size) {
    const int*   x      = (const int*)d_in[0];
    const float* emb    = (const float*)d_in[1];
    const float* conv_w = (const float*)d_in[2];
    const float* conv_b = (const float*)d_in[3];
    const float* W      = (const float*)d_in[4];
    const float* w1     = (const float*)d_in[5];
    const float* b1     = (const float*)d_in[6];
    const float* w2     = (const float*)d_in[7];
    const float* b2     = (const float*)d_in[8];
    const float* w3     = (const float*)d_in[9];
    const float* b3     = (const float*)d_in[10];
    float* out       = (float*)d_out;
    float* out_len   = out;                       // [64,50]
    float* out_recon = out + BATCH * NCAPS;       // [64,19000]

    static bool attr_done = false;
    if (!attr_done) {
        cudaFuncSetAttribute(k_pass_s<0>, cudaFuncAttributeMaxDynamicSharedMemorySize,
                             SMEM_S * (int)sizeof(float));
        cudaFuncSetAttribute(k_pass_s<1>, cudaFuncAttributeMaxDynamicSharedMemorySize,
                             SMEM_S * (int)sizeof(float));
        cudaFuncSetAttribute(k_pass_agree<0>, cudaFuncAttributeMaxDynamicSharedMemorySize,
                             SMEM_A * (int)sizeof(float));
        cudaFuncSetAttribute(k_pass_agree<1>, cudaFuncAttributeMaxDynamicSharedMemorySize,
                             SMEM_A * (int)sizeof(float));
        attr_done = true;
    }

    dim3 pass_grid(NRB, NCAPS);
    size_t sm_s = SMEM_S * sizeof(float);
    size_t sm_a = SMEM_A * sizeof(float);

    k_transpose_w<<<576, 256>>>(conv_w);
    k_conv<<<dim3(64, 6), 256>>>(x, emb, conv_b);

    // routing iter 0: uniform coupling
    k_pass_s<0><<<pass_grid, 256, sm_s>>>(W);
    k_finalize_v<<<200, 256>>>();

    // iter 1
    k_pass_agree<0><<<pass_grid, 256, sm_a>>>(W);
    k_coeff<<<768, 256>>>();
    k_pass_s<1><<<pass_grid, 256, sm_s>>>(W);
    k_finalize_v<<<200, 256>>>();

    // iter 2
    k_pass_agree<1><<<pass_grid, 256, sm_a>>>(W);
    k_coeff<<<768, 256>>>();
    k_pass_s<1><<<pass_grid, 256, sm_s>>>(W);
    k_finalize_v<<<200, 256>>>();

    // heads
    k_lengths<<<1, 64>>>(out_len);
    k_mlp1<<<64, 512>>>(w1, b1);
    k_mlp2<<<64, 256>>>(w2, b2);
    k_mlp3<<<149, 256>>>(w3, b3, out_recon);
}

// round 5
// speedup vs baseline: 1.8338x; 1.0017x over previous
#include <cuda_runtime.h>
#include <math.h>

#define BATCH   64
#define SEQ     200
#define EMBED   64
#define NCAPS   50
#define R_TOT   3072
#define LOUT    96
#define ODIM    16
#define RT      32          // routes per block in pass kernels
#define NRB     96          // R_TOT / RT

// ---------------- scratch (static device allocations; no cudaMalloc) -------
__device__ __align__(16) float g_cwt[576 * 256];                        // [ek][ch]
__device__ __align__(16) float g_u[(size_t)BATCH * R_TOT * 8];          // [b][r][i]
__device__ __align__(16) float g_blog[(size_t)NCAPS * R_TOT * BATCH];   // [c][r][b]
__device__ __align__(16) float g_coeff[(size_t)NCAPS * R_TOT * BATCH];  // [c][r][b]
__device__ __align__(16) float g_spart[(size_t)NCAPS * NRB * BATCH * 16]; // [c][rb][b][o]
__device__ __align__(16) float g_v[BATCH * NCAPS * 16];                 // [b][c][o]
__device__ __align__(16) float g_h1[BATCH * 512];
__device__ __align__(16) float g_h2[BATCH * 1024];
__device__ int   g_amax[BATCH];

// ---------------- f32x2 helpers --------------------------------------------
__device__ __forceinline__ unsigned long long pk2(float a, float b) {
    unsigned long long r;
    asm("mov.b64 %0, {%1, %2};" : "=l"(r) : "f"(a), "f"(b));
    return r;
}
__device__ __forceinline__ void fma2(unsigned long long& d, unsigned long long a,
                                     unsigned long long b) {
    asm("fma.rn.f32x2 %0, %1, %2, %0;" : "+l"(d) : "l"(a), "l"(b));
}
__device__ __forceinline__ unsigned long long add2(unsigned long long a,
                                                   unsigned long long b) {
    unsigned long long r;
    asm("add.rn.f32x2 %0, %1, %2;" : "=l"(r) : "l"(a), "l"(b));
    return r;
}
__device__ __forceinline__ float2 upk(unsigned long long v) {
    float2 f;
    asm("mov.b64 {%0, %1}, %2;" : "=f"(f.x), "=f"(f.y) : "l"(v));
    return f;
}

// ---------------- transpose conv weights: [ch][e][k] -> [e*9+k][ch] --------
__global__ void k_transpose_w(const float* __restrict__ conv_w) {
    int ek = blockIdx.x;
    int ch = threadIdx.x;
    g_cwt[ek * 256 + ch] = conv_w[ch * 576 + ek];
}

// ---------------- embedding + conv1d(k=9,s=2) + relu -> u ------------------
__global__ void k_conv(const int* __restrict__ x, const float* __restrict__ emb,
                       const float* __restrict__ conv_b) {
    int b = blockIdx.x;
    int l0 = blockIdx.y * 16;
    __shared__ float xs[39 * 64];
    const int tid = threadIdx.x;
    for (int idx = tid; idx < 39 * 16; idx += 256) {
        int row = idx >> 4, col = idx & 15;
        int tok = x[b * SEQ + 2 * l0 + row];
        ((float4*)xs)[row * 16 + col] = ((const float4*)(emb + (size_t)tok * EMBED))[col];
    }
    __syncthreads();
    int ch = tid;
    float acc[16];
    float bias = conv_b[ch];
#pragma unroll
    for (int j = 0; j < 16; j++) acc[j] = bias;
    for (int e = 0; e < 64; e++) {
#pragma unroll
        for (int k = 0; k < 9; k++) {
            float w = g_cwt[(e * 9 + k) * 256 + ch];
#pragma unroll
            for (int j = 0; j < 16; j++)
                acc[j] = fmaf(xs[(2 * j + k) * 64 + e], w, acc[j]);
        }
    }
    int g = ch >> 3, i = ch & 7;
#pragma unroll
    for (int j = 0; j < 16; j++) {
        float val = acc[j] > 0.f ? acc[j] : 0.f;
        g_u[((size_t)b * R_TOT + g * LOUT + l0 + j) * 8 + i] = val;
    }
}

// ---------------- pass_s: partial s over an r-block -------------------------
// grid (96 rb, 50 c), 256 thr. thread: rg = tid&7 (4 routes rl = rr*8+rg),
// bg = tid>>3 (2 batches). acc packed f32x2 over o-pairs. Butterfly-reduce
// over the 8 rg lanes, rg==0 writes g_spart[c][rb][b][o]. No atomics.
#define CF_STRIDE 68
#define SMEM_S (RT * 132 + RT * 516 + RT * CF_STRIDE)
template <int MODE>   // 0 = uniform 1/50, 1 = g_coeff
__global__ void __launch_bounds__(256, 2) k_pass_s(const float* __restrict__ W) {
    extern __shared__ float sh[];
    float* Ws    = sh;                       // RT rows x 132 (128 used)
    float* u_sh  = sh + RT * 132;            // RT rows x 516 (512 used)
    float* cf_sh = sh + RT * 132 + RT * 516; // RT rows x 68  (64 used)

    int c = blockIdx.y;
    int rb = blockIdx.x;
    int r0 = rb * RT;
    int tid = threadIdx.x;

    // stage W (coalesced)
    const float4* Wg = (const float4*)(W + ((size_t)c * R_TOT + r0) * 128);
    for (int idx = tid; idx < RT * 32; idx += 256) {
        int rl = idx >> 5, q = idx & 31;
        *(float4*)&Ws[rl * 132 + q * 4] = Wg[idx];
    }
    // stage u (coalesced: 1KB contiguous per batch)
    for (int idx = tid; idx < BATCH * RT * 2; idx += 256) {
        int b = idx >> 6;
        int t = idx & 63;
        int rl = t >> 1, i4 = (t & 1) * 4;
        float4 v = *(const float4*)(g_u + ((size_t)b * R_TOT + r0 + rl) * 8 + i4);
        *(float4*)&u_sh[rl * 516 + b * 8 + i4] = v;
    }
    if (MODE == 1) {
        for (int idx = tid; idx < RT * 16; idx += 256) {
            int rl = idx >> 4, b4 = (idx & 15) * 4;
            float4 v = *(const float4*)(g_coeff + ((size_t)c * R_TOT + r0 + rl) * 64 + b4);
            *(float4*)&cf_sh[rl * CF_STRIDE + b4] = v;
        }
    }
    __syncthreads();

    int rg = tid & 7;
    int bg = tid >> 3;
    int b0 = bg * 2;

    unsigned long long acc0[8], acc1[8];
#pragma unroll
    for (int k = 0; k < 8; k++) { acc0[k] = 0ull; acc1[k] = 0ull; }

#pragma unroll
    for (int rr = 0; rr < 4; rr++) {
        int rl = rr * 8 + rg;
        float cf0, cf1;
        if (MODE == 0) { cf0 = cf1 = 0.02f; }
        else {
            float2 t = *(const float2*)&cf_sh[rl * CF_STRIDE + b0];
            cf0 = t.x; cf1 = t.y;
        }
        const float* up = &u_sh[rl * 516 + b0 * 8];
        float4 a0 = *(const float4*)(up);
        float4 a1 = *(const float4*)(up + 4);
        float4 c0 = *(const float4*)(up + 8);
        float4 c1 = *(const float4*)(up + 12);
        float su0[8] = {cf0 * a0.x, cf0 * a0.y, cf0 * a0.z, cf0 * a0.w,
                        cf0 * a1.x, cf0 * a1.y, cf0 * a1.z, cf0 * a1.w};
        float su1[8] = {cf1 * c0.x, cf1 * c0.y, cf1 * c0.z, cf1 * c0.w,
                        cf1 * c1.x, cf1 * c1.y, cf1 * c1.z, cf1 * c1.w};
        const float* wrow = &Ws[rl * 132];
#pragma unroll
        for (int i = 0; i < 8; i++) {
            unsigned long long s0 = pk2(su0[i], su0[i]);
            unsigned long long s1 = pk2(su1[i], su1[i]);
#pragma unroll
            for (int o4 = 0; o4 < 4; o4++) {
                ulonglong2 wp = *(const ulonglong2*)&wrow[i * 16 + o4 * 4];
                fma2(acc0[o4 * 2 + 0], s0, wp.x);
                fma2(acc0[o4 * 2 + 1], s0, wp.y);
                fma2(acc1[o4 * 2 + 0], s1, wp.x);
                fma2(acc1[o4 * 2 + 1], s1, wp.y);
            }
        }
    }
    // reduce over the 8 rg lanes (contiguous in warp)
#pragma unroll
    for (int m = 1; m <= 4; m <<= 1) {
#pragma unroll
        for (int k = 0; k < 8; k++) {
            acc0[k] = add2(acc0[k], __shfl_xor_sync(0xffffffffu, acc0[k], m));
            acc1[k] = add2(acc1[k], __shfl_xor_sync(0xffffffffu, acc1[k], m));
        }
    }
    if (rg == 0) {
        unsigned long long* dst =
            (unsigned long long*)(g_spart + (((size_t)c * NRB + rb) * BATCH + b0) * 16);
#pragma unroll
        for (int k = 0; k < 8; k++) dst[k] = acc0[k];
#pragma unroll
        for (int k = 0; k < 8; k++) dst[8 + k] = acc1[k];
    }
}

// ---------------- reduce partials over rb + squash -> v ---------------------
__global__ void k_finalize_v() {
    int gid = blockIdx.x * 256 + threadIdx.x;   // (b*50+c)*16 + o, 51200 total
    int o = gid & 15;
    int bc = gid >> 4;
    int b = bc / NCAPS;
    int c = bc % NCAPS;
    float s = 0.f;
#pragma unroll 8
    for (int rb = 0; rb < NRB; rb++)
        s += g_spart[(((size_t)c * NRB + rb) * BATCH + b) * 16 + o];
    float nsq = s * s;
#pragma unroll
    for (int m = 1; m <= 8; m <<= 1)
        nsq += __shfl_xor_sync(0xffffffffu, nsq, m);
    float norm = sqrtf(nsq);
    float f = nsq / (1.f + nsq) / (norm + 1e-8f);
    g_v[gid] = f * s;
}

// ---------------- pass_agree: b_log[c,r,b] (+)= u_hat . v -------------------
#define SMEM_A (RT * 132 + RT * 516 + BATCH * 16)
template <int ACC>
__global__ void __launch_bounds__(256, 2) k_pass_agree(const float* __restrict__ W) {
    extern __shared__ float sh[];
    float* Ws   = sh;
    float* u_sh = sh + RT * 132;
    float* v_sh = sh + RT * 132 + RT * 516;

    int c = blockIdx.y;
    int rb = blockIdx.x;
    int r0 = rb * RT;
    int tid = threadIdx.x;

    const float4* Wg = (const float4*)(W + ((size_t)c * R_TOT + r0) * 128);
    for (int idx = tid; idx < RT * 32; idx += 256) {
        int rl = idx >> 5, q = idx & 31;
        *(float4*)&Ws[rl * 132 + q * 4] = Wg[idx];
    }
    for (int idx = tid; idx < BATCH * RT * 2; idx += 256) {
        int b = idx >> 6;
        int t = idx & 63;
        int rl = t >> 1, i4 = (t & 1) * 4;
        float4 v = *(const float4*)(g_u + ((size_t)b * R_TOT + r0 + rl) * 8 + i4);
        *(float4*)&u_sh[rl * 516 + b * 8 + i4] = v;
    }
    // v tile: all 64 batches for this c
    {
        int b = tid >> 2, o4 = (tid & 3) * 4;
        *(float4*)&v_sh[b * 16 + o4] =
            *(const float4*)(g_v + ((size_t)b * NCAPS + c) * 16 + o4);
    }
    __syncthreads();

    int rg = tid & 7;
    int bg = tid >> 3;
    int b0 = bg * 2;

    unsigned long long vp0[8], vp1[8];
    const unsigned long long* vr = (const unsigned long long*)&v_sh[b0 * 16];
#pragma unroll
    for (int k = 0; k < 8; k++) { vp0[k] = vr[k]; vp1[k] = vr[8 + k]; }

#pragma unroll
    for (int rr = 0; rr < 4; rr++) {
        int rl = rr * 8 + rg;
        int r = r0 + rl;
        const float* wrow = &Ws[rl * 132];
        float gg0[8], gg1[8];
#pragma unroll
        for (int i = 0; i < 8; i++) {
            unsigned long long gi0 = 0ull, gi1 = 0ull;
#pragma unroll
            for (int o4 = 0; o4 < 4; o4++) {
                ulonglong2 wp = *(const ulonglong2*)&wrow[i * 16 + o4 * 4];
                fma2(gi0, wp.x, vp0[o4 * 2 + 0]);
                fma2(gi0, wp.y, vp0[o4 * 2 + 1]);
                fma2(gi1, wp.x, vp1[o4 * 2 + 0]);
                fma2(gi1, wp.y, vp1[o4 * 2 + 1]);
            }
            float2 t0 = upk(gi0), t1 = upk(gi1);
            gg0[i] = t0.x + t0.y;
            gg1[i] = t1.x + t1.y;
        }
        const float* up = &u_sh[rl * 516 + b0 * 8];
        float4 a0 = *(const float4*)(up);
        float4 a1 = *(const float4*)(up + 4);
        float4 c0 = *(const float4*)(up + 8);
        float4 c1 = *(const float4*)(up + 12);
        float add0 = a0.x * gg0[0] + a0.y * gg0[1] + a0.z * gg0[2] + a0.w * gg0[3]
                   + a1.x * gg0[4] + a1.y * gg0[5] + a1.z * gg0[6] + a1.w * gg0[7];
        float add1 = c0.x * gg1[0] + c0.y * gg1[1] + c0.z * gg1[2] + c0.w * gg1[3]
                   + c1.x * gg1[4] + c1.y * gg1[5] + c1.z * gg1[6] + c1.w * gg1[7];
        float* dst = g_blog + ((size_t)c * R_TOT + r) * 64 + b0;
        float2 res = make_float2(add0, add1);
        if (ACC) {
            float2 old = *(const float2*)dst;
            res.x += old.x; res.y += old.y;
        }
        *(float2*)dst = res;
    }
}

// ---------------- coeff = softmax_c(b_log) ----------------------------------
__global__ void k_coeff() {
    int idx = blockIdx.x * 256 + threadIdx.x;   // r*64+b, 196608 total
    float e[NCAPS];
    float mx = -1e30f;
#pragma unroll
    for (int c = 0; c < NCAPS; c++) {
        e[c] = g_blog[(size_t)c * (R_TOT * 64) + idx];
        mx = fmaxf(mx, e[c]);
    }
    float sum = 0.f;
#pragma unroll
    for (int c = 0; c < NCAPS; c++) {
        e[c] = __expf(e[c] - mx);
        sum += e[c];
    }
    float iz = 1.f / sum;
#pragma unroll
    for (int c = 0; c < NCAPS; c++)
        g_coeff[(size_t)c * (R_TOT * 64) + idx] = e[c] * iz;
}

// ---------------- lengths + argmax ------------------------------------------
__global__ void k_lengths(float* __restrict__ out_len) {
    int b = threadIdx.x;
    if (b >= BATCH) return;
    float best = -1.f; int bi = 0;
    for (int c = 0; c < NCAPS; c++) {
        const float4* vp = (const float4*)(g_v + ((size_t)b * NCAPS + c) * 16);
        float nsq = 0.f;
#pragma unroll
        for (int o4 = 0; o4 < 4; o4++) {
            float4 t = vp[o4];
            nsq += t.x * t.x + t.y * t.y + t.z * t.z + t.w * t.w;
        }
        float len = sqrtf(nsq);
        out_len[b * NCAPS + c] = len;
        if (len > best) { best = len; bi = c; }
    }
    g_amax[b] = bi;
}

// ---------------- MLP layer 1 (16-sparse input) -----------------------------
__global__ void k_mlp1(const float* __restrict__ w1, const float* __restrict__ b1) {
    int b = blockIdx.x;
    int cb = g_amax[b];
    __shared__ float vv[16];
    if (threadIdx.x < 16)
        vv[threadIdx.x] = g_v[((size_t)b * NCAPS + cb) * 16 + threadIdx.x];
    __syncthreads();
    int n = threadIdx.x;
    float acc = b1[n];
#pragma unroll
    for (int o = 0; o < 16; o++)
        acc = fmaf(vv[o], w1[(size_t)(cb * 16 + o) * 512 + n], acc);
    g_h1[b * 512 + n] = acc > 0.f ? acc : 0.f;
}

// ---------------- MLP layer 2 ----------------------------------------------
__global__ void k_mlp2(const float* __restrict__ w2, const float* __restrict__ b2) {
    int b = blockIdx.x;
    __shared__ float hh[512];
    for (int i = threadIdx.x; i < 512; i += 256) hh[i] = g_h1[b * 512 + i];
    __syncthreads();
    int n0 = threadIdx.x * 4;
    float4 acc = *(const float4*)(b2 + n0);
    for (int k = 0; k < 512; k++) {
        float h = hh[k];
        float4 w = *(const float4*)(w2 + (size_t)k * 1024 + n0);
        acc.x = fmaf(h, w.x, acc.x);
        acc.y = fmaf(h, w.y, acc.y);
        acc.z = fmaf(h, w.z, acc.z);
        acc.w = fmaf(h, w.w, acc.w);
    }
    acc.x = acc.x > 0.f ? acc.x : 0.f;
    acc.y = acc.y > 0.f ? acc.y : 0.f;
    acc.z = acc.z > 0.f ? acc.z : 0.f;
    acc.w = acc.w > 0.f ? acc.w : 0.f;
    *(float4*)(g_h2 + (size_t)b * 1024 + n0) = acc;
}

// ---------------- MLP layer 3 (f32x2 over batch pairs) ----------------------
// grid = 149 n-tiles of 128; each block computes all 64 batch rows.
// thread: bt = tid>>5 -> 8 batches (4 pairs), ntid = tid&31 -> 4 n columns.
__global__ void k_mlp3(const float* __restrict__ w3, const float* __restrict__ b3,
                       float* __restrict__ out_recon) {
    int ncol0 = blockIdx.x * 128;
    __shared__ unsigned long long h2p[32 * 33];   // [b-pair][kk], padded
    __shared__ float w3s[32 * 128];
    int tid = threadIdx.x;
    int bt = tid >> 5, ntid = tid & 31;
    int bp0 = bt * 4;                 // first batch-pair
    int n_off = ntid * 4;
    unsigned long long acc2[4][4];
#pragma unroll
    for (int jp = 0; jp < 4; jp++)
#pragma unroll
        for (int e = 0; e < 4; e++) acc2[jp][e] = 0ull;

    for (int kc = 0; kc < 32; kc++) {
        for (int idx = tid; idx < 32 * 32; idx += 256) {
            int bp = idx >> 5, kk = idx & 31;
            float lo = g_h2[(size_t)(2 * bp) * 1024 + kc * 32 + kk];
            float hi = g_h2[(size_t)(2 * bp + 1) * 1024 + kc * 32 + kk];
            h2p[bp * 33 + kk] = pk2(lo, hi);
        }
        for (int idx = tid; idx < 32 * 32; idx += 256) {
            int kk = idx >> 5, jj = idx & 31;
            int col = ncol0 + jj * 4;
            float4 val;
            const float* row = w3 + (size_t)(kc * 32 + kk) * 19000;
            if (col + 3 < 19000) {
                val = *(const float4*)(row + col);
            } else {
                val.x = (col + 0 < 19000) ? row[col + 0] : 0.f;
                val.y = (col + 1 < 19000) ? row[col + 1] : 0.f;
                val.z = (col + 2 < 19000) ? row[col + 2] : 0.f;
                val.w = (col + 3 < 19000) ? row[col + 3] : 0.f;
            }
            *(float4*)&w3s[kk * 128 + jj * 4] = val;
        }
        __syncthreads();
        for (int kk = 0; kk < 32; kk++) {
            float4 w = *(const float4*)&w3s[kk * 128 + n_off];
            unsigned long long wp0 = pk2(w.x, w.x);
            unsigned long long wp1 = pk2(w.y, w.y);
            unsigned long long wp2 = pk2(w.z, w.z);
            unsigned long long wp3 = pk2(w.w, w.w);
#pragma unroll
            for (int jp = 0; jp < 4; jp++) {
                unsigned long long h = h2p[(bp0 + jp) * 33 + kk];
                fma2(acc2[jp][0], h, wp0);
                fma2(acc2[jp][1], h, wp1);
                fma2(acc2[jp][2], h, wp2);
                fma2(acc2[jp][3], h, wp3);
            }
        }
        __syncthreads();
    }
    int n = ncol0 + n_off;
#pragma unroll
    for (int jp = 0; jp < 4; jp++) {
        int b_even = (bp0 + jp) * 2;
#pragma unroll
        for (int e = 0; e < 4; e++) {
            int nn = n + e;
            if (nn < 19000) {
                float2 t = upk(acc2[jp][e]);
                float bias = b3[nn];
                float v0 = t.x + bias, v1 = t.y + bias;
                out_recon[(size_t)b_even * 19000 + nn] = 1.f / (1.f + __expf(-v0));
                out_recon[(size_t)(b_even + 1) * 19000 + nn] = 1.f / (1.f + __expf(-v1));
            }
        }
    }
}

// ---------------- launch ----------------------------------------------------
extern "C" void kernel_launch(void* const* d_in, const int* in_sizes, int n_in,
                              void* d_out, int out_size) {
    const int*   x      = (const int*)d_in[0];
    const float* emb    = (const float*)d_in[1];
    const float* conv_w = (const float*)d_in[2];
    const float* conv_b = (const float*)d_in[3];
    const float* W      = (const float*)d_in[4];
    const float* w1     = (const float*)d_in[5];
    const float* b1     = (const float*)d_in[6];
    const float* w2     = (const float*)d_in[7];
    const float* b2     = (const float*)d_in[8];
    const float* w3     = (const float*)d_in[9];
    const float* b3     = (const float*)d_in[10];
    float* out       = (float*)d_out;
    float* out_len   = out;                       // [64,50]
    float* out_recon = out + BATCH * NCAPS;       // [64,19000]

    static bool attr_done = false;
    if (!attr_done) {
        cudaFuncSetAttribute(k_pass_s<0>, cudaFuncAttributeMaxDynamicSharedMemorySize,
                             SMEM_S * (int)sizeof(float));
        cudaFuncSetAttribute(k_pass_s<1>, cudaFuncAttributeMaxDynamicSharedMemorySize,
                             SMEM_S * (int)sizeof(float));
        cudaFuncSetAttribute(k_pass_agree<0>, cudaFuncAttributeMaxDynamicSharedMemorySize,
                             SMEM_A * (int)sizeof(float));
        cudaFuncSetAttribute(k_pass_agree<1>, cudaFuncAttributeMaxDynamicSharedMemorySize,
                             SMEM_A * (int)sizeof(float));
        attr_done = true;
    }

    dim3 pass_grid(NRB, NCAPS);
    size_t sm_s = SMEM_S * sizeof(float);
    size_t sm_a = SMEM_A * sizeof(float);

    k_transpose_w<<<576, 256>>>(conv_w);
    k_conv<<<dim3(64, 6), 256>>>(x, emb, conv_b);

    // routing iter 0: uniform coupling
    k_pass_s<0><<<pass_grid, 256, sm_s>>>(W);
    k_finalize_v<<<200, 256>>>();

    // iter 1
    k_pass_agree<0><<<pass_grid, 256, sm_a>>>(W);
    k_coeff<<<768, 256>>>();
    k_pass_s<1><<<pass_grid, 256, sm_s>>>(W);
    k_finalize_v<<<200, 256>>>();

    // iter 2
    k_pass_agree<1><<<pass_grid, 256, sm_a>>>(W);
    k_coeff<<<768, 256>>>();
    k_pass_s<1><<<pass_grid, 256, sm_s>>>(W);
    k_finalize_v<<<200, 256>>>();

    // heads
    k_lengths<<<1, 64>>>(out_len);
    k_mlp1<<<64, 512>>>(w1, b1);
    k_mlp2<<<64, 256>>>(w2, b2);
    k_mlp3<<<149, 256>>>(w3, b3, out_recon);
}